// round 2
// baseline (speedup 1.0000x reference)
#include <cuda_runtime.h>

#define NPSI 256
#define MM 8
#define KK 4

__global__ __launch_bounds__(256, 8)
void eik_kernel(const float* __restrict__ t_ptr,
                const float* __restrict__ psi,
                const float* __restrict__ theta,
                const float* __restrict__ varphi,
                const float* __restrict__ q_vals,
                const float* __restrict__ aoff_vals,
                const float* __restrict__ theta0,
                const float* __restrict__ omega,
                const float* __restrict__ psi0,
                const float* __restrict__ psi_scale,
                const float* __restrict__ alpha_scale,
                const float* __restrict__ gh,      // [M,4,6]
                const int*   __restrict__ n_arr,
                float* __restrict__ out, int N)
{
    __shared__ float s_q[NPSI], s_gq[NPSI], s_a[NPSI], s_ga[NPSI];
    __shared__ float s_c[MM * 24];
    __shared__ float s_th0[MM], s_ps0[MM], s_ips[MM], s_ias[MM],
                     s_as[MM], s_omt[MM], s_nf[MM];

    const int tid = threadIdx.x;

    // Stage tables into shared
    if (tid < NPSI) {
        s_q[tid] = q_vals[tid];
        s_a[tid] = aoff_vals[tid];
    }
    if (tid < MM * 24) s_c[tid] = gh[tid];
    if (tid < MM) {
        float t = t_ptr[0];
        s_th0[tid] = theta0[tid];
        s_ps0[tid] = psi0[tid];
        s_ips[tid] = 1.0f / psi_scale[tid];
        float as = alpha_scale[tid];
        s_as[tid]  = as;
        s_ias[tid] = 1.0f / as;
        s_omt[tid] = omega[tid] * t;
        s_nf[tid]  = (float)n_arr[tid];
    }
    __syncthreads();

    // Index-space FD gradients (jnp.gradient semantics): H*d = grad in index units
    if (tid < NPSI) {
        float gq, ga;
        if (tid == 0)            { gq = s_q[1] - s_q[0];           ga = s_a[1] - s_a[0]; }
        else if (tid == NPSI-1)  { gq = s_q[NPSI-1] - s_q[NPSI-2]; ga = s_a[NPSI-1] - s_a[NPSI-2]; }
        else                     { gq = 0.5f * (s_q[tid+1] - s_q[tid-1]);
                                   ga = 0.5f * (s_a[tid+1] - s_a[tid-1]); }
        s_gq[tid] = gq;
        s_ga[tid] = ga;
    }
    __syncthreads();

    const int i = blockIdx.x * blockDim.x + tid;
    if (i >= N) return;

    const float p  = psi[i];
    const float th = theta[i];
    const float vp = varphi[i];

    // Cubic Hermite interp of (q, aoff) at psi
    float u = p * (float)(NPSI - 1);
    int i0 = (int)floorf(u);
    i0 = min(max(i0, 0), NPSI - 2);
    float s  = u - (float)i0;
    float s2 = s * s;
    float s3 = s2 * s;
    float w0 = 2.0f*s3 - 3.0f*s2 + 1.0f;
    float w1 = s3 - 2.0f*s2 + s;
    float w2 = 3.0f*s2 - 2.0f*s3;
    float w3 = s3 - s2;
    float q  = w0*s_q[i0] + w1*s_gq[i0] + w2*s_q[i0+1] + w3*s_gq[i0+1];
    float ao = w0*s_a[i0] + w1*s_ga[i0] + w2*s_a[i0+1] + w3*s_ga[i0+1];
    (void)ao; // aoff cancels in y and phase; kept for clarity

    const float TWO_PI = 6.283185307179586f;

    float acc_phi = 0.0f;
    float acc_apar = 0.0f;

    #pragma unroll
    for (int m = 0; m < MM; m++) {
        const float x   = (p - s_ps0[m]) * s_ips[m];
        const float x2  = x * x;
        const float h20 = 4.0f * x2 - 2.0f;

        // y_k = q*(theta + 2*pi*k - theta0[m]) / alpha_scale[m]
        const float ias   = s_ias[m];
        const float ybase = q * (th - s_th0[m]) * ias;
        const float ystep = q * TWO_PI * ias;

        // phase = omega*t - n*varphi + (n*alpha_scale)*y
        const float nf    = s_nf[m];
        const float pbase = s_omt[m] - nf * vp;
        const float pcoef = nf * s_as[m];

        const float* c = &s_c[m * 24];
        const float c00=c[0],  c01=c[1],  c02=c[2],  c03=c[3],  c04=c[4],  c05=c[5];
        const float c10=c[6],  c11=c[7],  c12=c[8],  c13=c[9],  c14=c[10], c15=c[11];
        const float c20=c[12], c21=c[13], c22=c[14], c23=c[15], c24=c[16], c25=c[17];
        const float c30=c[18], c31=c[19], c32=c[20], c33=c[21], c34=c[22], c35=c[23];

        #pragma unroll
        for (int k = 0; k < KK; k++) {
            const float y   = fmaf((float)k, ystep, ybase);
            const float y2  = y * y;
            const float h02 = 4.0f * y2 - 2.0f;
            const float xy  = x * y;

            const float g = __expf(-0.5f * (x2 + y2));

            float sp, cp;
            __sincosf(fmaf(pcoef, y, pbase), &sp, &cp);
            const float cg = cp * g;
            const float sg = sp * g;

            const float p0 = c00 + c01*x + c02*y + c03*h20 + c04*xy + c05*h02;
            const float p1 = c10 + c11*x + c12*y + c13*h20 + c14*xy + c15*h02;
            const float p2 = c20 + c21*x + c22*y + c23*h20 + c24*xy + c25*h02;
            const float p3 = c30 + c31*x + c32*y + c33*h20 + c34*xy + c35*h02;

            acc_phi  = fmaf(p0, cg, fmaf(-p1, sg, acc_phi));
            acc_apar = fmaf(p2, cg, fmaf(-p3, sg, acc_apar));
        }
    }

    out[i]     = acc_phi;
    out[N + i] = acc_apar;
}

extern "C" void kernel_launch(void* const* d_in, const int* in_sizes, int n_in,
                              void* d_out, int out_size) {
    const float* t_ptr    = (const float*)d_in[0];
    const float* psi      = (const float*)d_in[1];
    const float* theta    = (const float*)d_in[2];
    const float* varphi   = (const float*)d_in[3];
    const float* q_vals   = (const float*)d_in[4];
    const float* aoff     = (const float*)d_in[5];
    const float* theta0   = (const float*)d_in[6];
    const float* omega    = (const float*)d_in[7];
    const float* psi0     = (const float*)d_in[8];
    const float* psi_sc   = (const float*)d_in[9];
    const float* alpha_sc = (const float*)d_in[10];
    const float* gh       = (const float*)d_in[11];
    const int*   n_arr    = (const int*)d_in[12];
    float* out = (float*)d_out;

    const int N = in_sizes[1];
    const int threads = 256;
    const int blocks = (N + threads - 1) / threads;
    eik_kernel<<<blocks, threads>>>(t_ptr, psi, theta, varphi, q_vals, aoff,
                                    theta0, omega, psi0, psi_sc, alpha_sc,
                                    gh, n_arr, out, N);
}

// round 3
// speedup vs baseline: 4.2071x; 4.2071x over previous
#include <cuda_runtime.h>

#define NPSI 256
#define MM 8
#define KK 4

__global__ __launch_bounds__(256, 6)
void eik_kernel(const float* __restrict__ t_ptr,
                const float* __restrict__ psi,
                const float* __restrict__ theta,
                const float* __restrict__ varphi,
                const float* __restrict__ q_vals,
                const float* __restrict__ aoff_vals,
                const float* __restrict__ theta0,
                const float* __restrict__ omega,
                const float* __restrict__ psi0,
                const float* __restrict__ psi_scale,
                const float* __restrict__ alpha_scale,
                const float* __restrict__ gh,      // [M,4,6]
                const int*   __restrict__ n_arr,
                float* __restrict__ out, int N)
{
    __shared__ float s_q[NPSI], s_gq[NPSI], s_a[NPSI], s_ga[NPSI];
    __shared__ __align__(16) float s_c[MM * 24];
    __shared__ float s_th0[MM], s_ps0[MM], s_ips[MM], s_ias[MM],
                     s_omt[MM], s_nf[MM];

    const int tid = threadIdx.x;

    if (tid < NPSI) {
        s_q[tid] = q_vals[tid];
        s_a[tid] = aoff_vals[tid];
    }
    if (tid < MM * 24) s_c[tid] = gh[tid];
    if (tid < MM) {
        float t = t_ptr[0];
        s_th0[tid] = theta0[tid];
        s_ps0[tid] = psi0[tid];
        s_ips[tid] = 1.0f / psi_scale[tid];
        s_ias[tid] = 1.0f / alpha_scale[tid];
        s_omt[tid] = omega[tid] * t;
        s_nf[tid]  = (float)n_arr[tid];
    }
    __syncthreads();

    // Index-space FD gradients (jnp.gradient): H*d == grad in index units
    if (tid < NPSI) {
        float gq, ga;
        if (tid == 0)            { gq = s_q[1] - s_q[0];           ga = s_a[1] - s_a[0]; }
        else if (tid == NPSI-1)  { gq = s_q[NPSI-1] - s_q[NPSI-2]; ga = s_a[NPSI-1] - s_a[NPSI-2]; }
        else                     { gq = 0.5f * (s_q[tid+1] - s_q[tid-1]);
                                   ga = 0.5f * (s_a[tid+1] - s_a[tid-1]); }
        s_gq[tid] = gq;
        s_ga[tid] = ga;
    }
    __syncthreads();

    const int i = blockIdx.x * blockDim.x + tid;
    if (i >= N) return;

    const float p  = psi[i];
    const float th = theta[i];
    const float vp = varphi[i];

    // Cubic Hermite interp of q at psi (aoff cancels everywhere downstream)
    float u = p * (float)(NPSI - 1);
    int i0 = (int)floorf(u);
    i0 = min(max(i0, 0), NPSI - 2);
    float s  = u - (float)i0;
    float s2 = s * s;
    float s3 = s2 * s;
    float w0 = 2.0f*s3 - 3.0f*s2 + 1.0f;
    float w1 = s3 - 2.0f*s2 + s;
    float w2 = 3.0f*s2 - 2.0f*s3;
    float w3 = s3 - s2;
    float q  = w0*s_q[i0] + w1*s_gq[i0] + w2*s_q[i0+1] + w3*s_gq[i0+1];

    const float TWO_PI = 6.283185307179586f;

    float acc_phi = 0.0f;
    float acc_apar = 0.0f;

    #pragma unroll
    for (int m = 0; m < MM; m++) {
        const float x   = (p - s_ps0[m]) * s_ips[m];
        const float x2  = x * x;
        const float h20 = 4.0f * x2 - 2.0f;

        const float ias   = s_ias[m];
        const float ybase = q * (th - s_th0[m]) * ias;
        const float ystep = q * TWO_PI * ias;

        // phase_k = (omt - n*vp) + (n/ias)*y_k ; step in k = 2*pi*n*q
        const float nf     = s_nf[m];
        const float phase0 = fmaf(nf / ias, ybase, s_omt[m] - nf * vp);
        const float dlt    = TWO_PI * nf * q;

        float sp, cp, sd, cd;
        __sincosf(phase0, &sp, &cp);
        __sincosf(dlt,    &sd, &cd);

        // Coefs as float4: c[j] = {c_j0..c_j5}, 24 floats per m
        const float4* c4 = (const float4*)&s_c[m * 24];
        const float4 ca = c4[0];  // c00 c01 c02 c03
        const float4 cb = c4[1];  // c04 c05 c10 c11
        const float4 cc = c4[2];  // c12 c13 c14 c15
        const float4 cd4= c4[3];  // c20 c21 c22 c23
        const float4 ce = c4[4];  // c24 c25 c30 c31
        const float4 cf = c4[5];  // c32 c33 c34 c35

        // p_j = A_j + B_j*y + C5_j*h02,  A_j = c_j0 + c_j1*x + c_j3*h20, B_j = c_j2 + c_j4*x
        const float A0 = fmaf(ca.w, h20, fmaf(ca.y, x, ca.x));
        const float B0 = fmaf(cb.x, x, ca.z);
        const float C0 = cb.y;
        const float A1 = fmaf(cc.y, h20, fmaf(cb.w, x, cb.z));
        const float B1 = fmaf(cc.z, x, cc.x);
        const float C1 = cc.w;
        const float A2 = fmaf(cd4.w, h20, fmaf(cd4.y, x, cd4.x));
        const float B2 = fmaf(ce.x, x, cd4.z);
        const float C2 = ce.y;
        const float A3 = fmaf(cf.y, h20, fmaf(ce.w, x, ce.z));
        const float B3 = fmaf(cf.z, x, cf.x);
        const float C3 = cf.w;

        float y = ybase;
        #pragma unroll
        for (int k = 0; k < KK; k++) {
            const float y2  = y * y;
            const float h02 = 4.0f * y2 - 2.0f;

            const float g  = __expf(-0.5f * (x2 + y2));
            const float cg = cp * g;
            const float sg = sp * g;

            const float p0 = fmaf(B0, y, fmaf(C0, h02, A0));
            const float p1 = fmaf(B1, y, fmaf(C1, h02, A1));
            const float p2 = fmaf(B2, y, fmaf(C2, h02, A2));
            const float p3 = fmaf(B3, y, fmaf(C3, h02, A3));

            acc_phi  = fmaf(p0, cg, fmaf(-p1, sg, acc_phi));
            acc_apar = fmaf(p2, cg, fmaf(-p3, sg, acc_apar));

            // rotate phase by dlt; advance y
            const float ncp = fmaf(cp, cd, -sp * sd);
            const float nsp = fmaf(sp, cd,  cp * sd);
            cp = ncp; sp = nsp;
            y += ystep;
        }
    }

    out[i]     = acc_phi;
    out[N + i] = acc_apar;
}

extern "C" void kernel_launch(void* const* d_in, const int* in_sizes, int n_in,
                              void* d_out, int out_size) {
    const float* t_ptr    = (const float*)d_in[0];
    const float* psi      = (const float*)d_in[1];
    const float* theta    = (const float*)d_in[2];
    const float* varphi   = (const float*)d_in[3];
    const float* q_vals   = (const float*)d_in[4];
    const float* aoff     = (const float*)d_in[5];
    const float* theta0   = (const float*)d_in[6];
    const float* omega    = (const float*)d_in[7];
    const float* psi0     = (const float*)d_in[8];
    const float* psi_sc   = (const float*)d_in[9];
    const float* alpha_sc = (const float*)d_in[10];
    const float* gh       = (const float*)d_in[11];
    const int*   n_arr    = (const int*)d_in[12];
    float* out = (float*)d_out;

    const int N = in_sizes[1];
    const int threads = 256;
    const int blocks = (N + threads - 1) / threads;
    eik_kernel<<<blocks, threads>>>(t_ptr, psi, theta, varphi, q_vals, aoff,
                                    theta0, omega, psi0, psi_sc, alpha_sc,
                                    gh, n_arr, out, N);
}

// round 4
// speedup vs baseline: 4.7762x; 1.1353x over previous
#include <cuda_runtime.h>

#define NPSI 256
#define MM 8
#define KK 4

typedef unsigned long long u64;

__device__ __forceinline__ u64 pk2(float lo, float hi) {
    u64 r; asm("mov.b64 %0, {%1, %2};" : "=l"(r) : "f"(lo), "f"(hi)); return r;
}
__device__ __forceinline__ void up2(u64 v, float& lo, float& hi) {
    asm("mov.b64 {%0, %1}, %2;" : "=f"(lo), "=f"(hi) : "l"(v));
}
__device__ __forceinline__ u64 ffma2(u64 a, u64 b, u64 c) {
    u64 d; asm("fma.rn.f32x2 %0, %1, %2, %3;" : "=l"(d) : "l"(a), "l"(b), "l"(c)); return d;
}
__device__ __forceinline__ float ex2a(float x) {
    float r; asm("ex2.approx.f32 %0, %1;" : "=f"(r) : "f"(x)); return r;
}

__global__ __launch_bounds__(256, 4)
void eik_kernel(const float* __restrict__ t_ptr,
                const float* __restrict__ psi,
                const float* __restrict__ theta,
                const float* __restrict__ varphi,
                const float* __restrict__ q_vals,
                const float* __restrict__ theta0,
                const float* __restrict__ omega,
                const float* __restrict__ psi0,
                const float* __restrict__ psi_scale,
                const float* __restrict__ alpha_scale,
                const float* __restrict__ gh,      // [M,4,6]
                const int*   __restrict__ n_arr,
                float* __restrict__ out, int N)
{
    __shared__ float s_q[NPSI], s_gq[NPSI];
    __shared__ __align__(16) float s_c[MM * 24];
    __shared__ float s_th0[MM], s_ps0[MM], s_ips[MM], s_ias[MM],
                     s_as[MM], s_omt[MM], s_nf[MM];

    const int tid = threadIdx.x;

    if (tid < NPSI) s_q[tid] = q_vals[tid];
    if (tid < MM * 24) s_c[tid] = gh[tid];
    if (tid < MM) {
        float t = t_ptr[0];
        s_th0[tid] = theta0[tid];
        s_ps0[tid] = psi0[tid];
        s_ips[tid] = 1.0f / psi_scale[tid];
        float as = alpha_scale[tid];
        s_as[tid]  = as;
        s_ias[tid] = 1.0f / as;
        s_omt[tid] = omega[tid] * t;
        s_nf[tid]  = (float)n_arr[tid];
    }
    __syncthreads();

    // jnp.gradient in index space (H*d == index-space grad)
    if (tid < NPSI) {
        float gq;
        if (tid == 0)           gq = s_q[1] - s_q[0];
        else if (tid == NPSI-1) gq = s_q[NPSI-1] - s_q[NPSI-2];
        else                    gq = 0.5f * (s_q[tid+1] - s_q[tid-1]);
        s_gq[tid] = gq;
    }
    __syncthreads();

    const int i = blockIdx.x * blockDim.x + tid;
    if (i >= N) return;

    const float p  = psi[i];
    const float th = theta[i];
    const float vp = varphi[i];

    // Cubic Hermite interp of q at psi (aoff cancels everywhere downstream)
    float u = p * (float)(NPSI - 1);
    int i0 = (int)floorf(u);
    i0 = min(max(i0, 0), NPSI - 2);
    float s  = u - (float)i0;
    float s2 = s * s;
    float s3 = s2 * s;
    float w0 = 2.0f*s3 - 3.0f*s2 + 1.0f;
    float w1 = s3 - 2.0f*s2 + s;
    float w2 = 3.0f*s2 - 2.0f*s3;
    float w3 = s3 - s2;
    float q  = w0*s_q[i0] + w1*s_gq[i0] + w2*s_q[i0+1] + w3*s_gq[i0+1];

    const float TWO_PI = 6.283185307179586f;
    const float NHL2E  = -0.72134752044448170f;   // -0.5 * log2(e)

    u64 acc01 = 0ULL;   // lanes: (sum p0*cg, sum -p1*sg)
    u64 acc23 = 0ULL;   // lanes: (sum p2*cg, sum -p3*sg)

    #pragma unroll
    for (int m = 0; m < MM; m++) {
        const float x   = (p - s_ps0[m]) * s_ips[m];
        const float x2  = x * x;
        const float h20 = 4.0f * x2 - 2.0f;
        const float xt  = x2 * NHL2E;             // exp2 arg contribution of x

        const float ias   = s_ias[m];
        const float ybase = q * (th - s_th0[m]) * ias;
        const float ystep = q * TWO_PI * ias;

        const float nf    = s_nf[m];
        const float pbase = s_omt[m] - nf * vp;
        const float pcoef = nf * s_as[m];

        const float4* c4 = (const float4*)&s_c[m * 24];
        const float4 ca = c4[0];   // c00 c01 c02 c03
        const float4 cb = c4[1];   // c04 c05 c10 c11
        const float4 cc = c4[2];   // c12 c13 c14 c15
        const float4 cdv= c4[3];   // c20 c21 c22 c23
        const float4 ce = c4[4];   // c24 c25 c30 c31
        const float4 cf = c4[5];   // c32 c33 c34 c35

        // p_j(y) = A'_j + B_j*y + (4 c_j5) y^2,  A'_j = c_j0 + c_j1 x + c_j3 h20 - 2 c_j5
        const float A0 = fmaf(ca.w, h20, fmaf(ca.y, x, ca.x)) - 2.0f*cb.y;
        const float B0 = fmaf(cb.x, x, ca.z);
        const float C0 = 4.0f*cb.y;
        const float A1 = fmaf(cc.y, h20, fmaf(cb.w, x, cb.z)) - 2.0f*cc.w;
        const float B1 = fmaf(cc.z, x, cc.x);
        const float C1 = 4.0f*cc.w;
        const float A2 = fmaf(cdv.w, h20, fmaf(cdv.y, x, cdv.x)) - 2.0f*ce.y;
        const float B2 = fmaf(ce.x, x, cdv.z);
        const float C2 = 4.0f*ce.y;
        const float A3 = fmaf(cf.y, h20, fmaf(ce.w, x, ce.z)) - 2.0f*cf.w;
        const float B3 = fmaf(cf.z, x, cf.x);
        const float C3 = 4.0f*cf.w;

        const u64 A01 = pk2(A0, A1), B01 = pk2(B0, B1), C01 = pk2(C0, C1);
        const u64 A23 = pk2(A2, A3), B23 = pk2(B2, B3), C23 = pk2(C2, C3);

        float y = ybase;
        #pragma unroll
        for (int k = 0; k < KK; k++) {
            const float y2 = y * y;
            const float g  = ex2a(fmaf(y2, NHL2E, xt));   // exp(-0.5(x^2+y^2))

            float sp, cp;
            __sincosf(fmaf(pcoef, y, pbase), &sp, &cp);

            const u64 yy = pk2(y, y);
            const u64 w  = pk2(cp * g, -sp * g);          // (cg, -sg)

            const u64 P01 = ffma2(ffma2(C01, yy, B01), yy, A01);
            const u64 P23 = ffma2(ffma2(C23, yy, B23), yy, A23);

            acc01 = ffma2(P01, w, acc01);
            acc23 = ffma2(P23, w, acc23);

            y += ystep;
        }
    }

    float a, b;
    up2(acc01, a, b);
    out[i] = a + b;
    up2(acc23, a, b);
    out[N + i] = a + b;
}

extern "C" void kernel_launch(void* const* d_in, const int* in_sizes, int n_in,
                              void* d_out, int out_size) {
    const float* t_ptr    = (const float*)d_in[0];
    const float* psi      = (const float*)d_in[1];
    const float* theta    = (const float*)d_in[2];
    const float* varphi   = (const float*)d_in[3];
    const float* q_vals   = (const float*)d_in[4];
    const float* theta0   = (const float*)d_in[6];
    const float* omega    = (const float*)d_in[7];
    const float* psi0     = (const float*)d_in[8];
    const float* psi_sc   = (const float*)d_in[9];
    const float* alpha_sc = (const float*)d_in[10];
    const float* gh       = (const float*)d_in[11];
    const int*   n_arr    = (const int*)d_in[12];
    float* out = (float*)d_out;

    const int N = in_sizes[1];
    const int threads = 256;
    const int blocks = (N + threads - 1) / threads;
    eik_kernel<<<blocks, threads>>>(t_ptr, psi, theta, varphi, q_vals,
                                    theta0, omega, psi0, psi_sc, alpha_sc,
                                    gh, n_arr, out, N);
}